// round 2
// baseline (speedup 1.0000x reference)
#include <cuda_runtime.h>
#include <math.h>

// x: [B=2, T=64, C=16, H=128, W=128] f32; qkv conv 3x3 pad1 (16->16),
// nh=8, hc=2, D=32768; causal softmax T=64; out conv 3x3 (16->16).
#define HW 16384

// ---------------- packed fp32x2 helpers (FFMA2 path, 2x fp32 tput) --------
__device__ __forceinline__ unsigned long long pk2(float lo, float hi) {
    unsigned long long r;
    asm("mov.b64 %0, {%1, %2};"
        : "=l"(r) : "r"(__float_as_uint(lo)), "r"(__float_as_uint(hi)));
    return r;
}
__device__ __forceinline__ void fma2(unsigned long long& d,
                                     unsigned long long a, unsigned long long b) {
    asm("fma.rn.f32x2 %0, %1, %2, %0;" : "+l"(d) : "l"(a), "l"(b));
}
__device__ __forceinline__ float2 upk(unsigned long long v) {
    unsigned lo, hi;
    asm("mov.b64 {%0, %1}, %2;" : "=r"(lo), "=r"(hi) : "l"(v));
    return make_float2(__uint_as_float(lo), __uint_as_float(hi));
}

// ---------------- scratch ----------------
__device__ float g_q[2*64*16*16384];   // q, later reused as attention output y
__device__ float g_k[2*64*16*16384];
__device__ float g_v[2*64*16*16384];
__device__ float g_part[64*16*64*64];  // QK^T partials per k-split
__device__ float g_att[16*64*64];      // softmax probs, [bh][s][t]

// ---------------- fused 3x3 conv (NCONV=3: qkv, NCONV=1: output) ----------
// Block 256 thr, tile 32(w) x 8(h), all NCONV*16 output channels.
// Thread = 4 pixels (2 packed pairs) x (NCONV*16/4) channels. FFMA2 inner.
template<int NCONV>
__global__ void __launch_bounds__(256) conv3x3_kernel(
    const float* __restrict__ xin,
    const float* __restrict__ w0, const float* __restrict__ b0,
    const float* __restrict__ w1, const float* __restrict__ b1,
    const float* __restrict__ w2, const float* __restrict__ b2,
    float* __restrict__ out_final)
{
    constexpr int NCH = NCONV * 16;
    constexpr int CPG = NCH / 4;
    extern __shared__ unsigned long long dynsmem[];
    unsigned long long* s_w2 = dynsmem;                 // NCH*16*10 packed (w,w)
    float* s_in = (float*)(dynsmem + NCH*160);          // 16*10*35 halo tile
    float* s_b  = s_in + 5600;                          // NCH biases

    const int tid = threadIdx.x;
    const int bt  = blockIdx.y;
    const int th0 = (blockIdx.x >> 2) * 8;
    const int tw0 = (blockIdx.x & 3) * 32;

    const float* x = (NCONV == 3) ? xin : g_q;

    // stage weights duplicated into both f32x2 lanes
    {
        const float* wsrc[3] = {w0, w1, w2};
        for (int idx = tid; idx < NCH*144; idx += 256) {
            int conv = idx / 2304;
            int rem  = idx - conv*2304;     // oc*144 + ic*9 + j
            int oc   = rem / 144;
            int r2   = rem - oc*144;
            int ic   = r2 / 9;
            int j    = r2 - ic*9;
            unsigned bbits = __float_as_uint(wsrc[conv][rem]);
            s_w2[((conv*16 + oc)*16 + ic)*10 + j] =
                ((unsigned long long)bbits << 32) | bbits;
        }
        for (int idx = tid; idx < NCH; idx += 256) {
            float bv;
            if (NCONV == 3) bv = (idx < 16) ? b0[idx] : (idx < 32 ? b1[idx-16] : b2[idx-32]);
            else            bv = b0[idx];
            s_b[idx] = bv;
        }
    }

    // stage input tile with halo
    for (int idx = tid; idx < 16*10*34; idx += 256) {
        int c   = idx / 340;
        int rem = idx - c*340;
        int yy  = rem / 34;
        int xx  = rem - yy*34;
        int gh  = th0 + yy - 1;
        int gw  = tw0 + xx - 1;
        float v = 0.f;
        if (gh >= 0 && gh < 128 && gw >= 0 && gw < 128)
            v = x[((size_t)bt*16 + c)*HW + gh*128 + gw];
        s_in[c*350 + yy*35 + xx] = v;
    }
    __syncthreads();

    const int pg = tid & 63;
    const int cg = tid >> 6;
    const int py = pg >> 3;
    const int x0 = (pg & 7) * 4;

    unsigned long long acc2[CPG][2];
#pragma unroll
    for (int c = 0; c < CPG; ++c) {
        float bb = s_b[cg*CPG + c];
        acc2[c][0] = pk2(bb, bb);
        acc2[c][1] = acc2[c][0];
    }

    for (int ic = 0; ic < 16; ++ic) {
        const float* base = s_in + ic*350 + py*35 + x0;
        float p[3][6];
#pragma unroll
        for (int ky = 0; ky < 3; ++ky)
#pragma unroll
            for (int kx = 0; kx < 6; ++kx)
                p[ky][kx] = base[ky*35 + kx];
        unsigned long long pkk[3][5];
#pragma unroll
        for (int ky = 0; ky < 3; ++ky)
#pragma unroll
            for (int j = 0; j < 5; ++j)
                pkk[ky][j] = pk2(p[ky][j], p[ky][j+1]);

#pragma unroll
        for (int c = 0; c < CPG; ++c) {
            const unsigned long long* wp = s_w2 + ((cg*CPG + c)*16 + ic)*10;
            ulonglong2 w01 = *(const ulonglong2*)wp;
            ulonglong2 w23 = *(const ulonglong2*)(wp + 2);
            ulonglong2 w45 = *(const ulonglong2*)(wp + 4);
            ulonglong2 w67 = *(const ulonglong2*)(wp + 6);
            unsigned long long w8 = wp[8];
            // pixel pair 0 (cols x0+0, x0+1)
            fma2(acc2[c][0], pkk[0][0], w01.x);
            fma2(acc2[c][0], pkk[0][1], w01.y);
            fma2(acc2[c][0], pkk[0][2], w23.x);
            fma2(acc2[c][0], pkk[1][0], w23.y);
            fma2(acc2[c][0], pkk[1][1], w45.x);
            fma2(acc2[c][0], pkk[1][2], w45.y);
            fma2(acc2[c][0], pkk[2][0], w67.x);
            fma2(acc2[c][0], pkk[2][1], w67.y);
            fma2(acc2[c][0], pkk[2][2], w8);
            // pixel pair 1 (cols x0+2, x0+3)
            fma2(acc2[c][1], pkk[0][2], w01.x);
            fma2(acc2[c][1], pkk[0][3], w01.y);
            fma2(acc2[c][1], pkk[0][4], w23.x);
            fma2(acc2[c][1], pkk[1][2], w23.y);
            fma2(acc2[c][1], pkk[1][3], w45.x);
            fma2(acc2[c][1], pkk[1][4], w45.y);
            fma2(acc2[c][1], pkk[2][2], w67.x);
            fma2(acc2[c][1], pkk[2][3], w67.y);
            fma2(acc2[c][1], pkk[2][4], w8);
        }
    }

    const int oh = th0 + py;
    const int ow = tw0 + x0;
#pragma unroll
    for (int c = 0; c < CPG; ++c) {
        int ch   = cg*CPG + c;
        int conv = ch >> 4;
        int oc   = ch & 15;
        size_t off = ((size_t)bt*16 + oc)*HW + oh*128 + ow;
        float2 a = upk(acc2[c][0]);
        float2 b = upk(acc2[c][1]);
        float4 val = make_float4(a.x, a.y, b.x, b.y);
        float* outp;
        if (NCONV == 3) outp = (conv == 0) ? g_q : (conv == 1 ? g_k : g_v);
        else            outp = out_final;
        *(float4*)(outp + off) = val;
    }
}

// ---------------- QK^T with K-split, FFMA2 inner ----------------
__global__ void __launch_bounds__(256) qk_kernel()
{
    __shared__ __align__(16) float Qs[64][68];
    __shared__ __align__(16) float Ks[64][68];
    const int bh = blockIdx.y;
    const int b  = bh >> 3, h = bh & 7;
    const int split = blockIdx.x;
    const int tid = threadIdx.x;
    const int ty = tid >> 4, tx = tid & 15;

    unsigned long long acc2[4][2];
#pragma unroll
    for (int i = 0; i < 4; ++i) { acc2[i][0] = 0ULL; acc2[i][1] = 0ULL; }

    for (int sub = 0; sub < 8; ++sub) {
        const int kc = split*512 + sub*64;
        __syncthreads();
        for (int i = tid; i < 1024; i += 256) {
            int t  = i >> 4;
            int kq = (i & 15) << 2;
            size_t base = ((size_t)((b*64 + t)*16 + h*2))*HW + kc + kq;
            float4 qa = *(const float4*)(g_q + base);
            float4 ka = *(const float4*)(g_k + base);
            Qs[kq+0][t] = qa.x; Qs[kq+1][t] = qa.y; Qs[kq+2][t] = qa.z; Qs[kq+3][t] = qa.w;
            Ks[kq+0][t] = ka.x; Ks[kq+1][t] = ka.y; Ks[kq+2][t] = ka.z; Ks[kq+3][t] = ka.w;
        }
        __syncthreads();
#pragma unroll 8
        for (int kk = 0; kk < 64; ++kk) {
            float4 a = *(const float4*)&Qs[kk][ty*4];
            ulonglong2 bp = *(const ulonglong2*)&Ks[kk][tx*4];
            unsigned long long a0 = pk2(a.x, a.x);
            unsigned long long a1 = pk2(a.y, a.y);
            unsigned long long a2 = pk2(a.z, a.z);
            unsigned long long a3 = pk2(a.w, a.w);
            fma2(acc2[0][0], a0, bp.x); fma2(acc2[0][1], a0, bp.y);
            fma2(acc2[1][0], a1, bp.x); fma2(acc2[1][1], a1, bp.y);
            fma2(acc2[2][0], a2, bp.x); fma2(acc2[2][1], a2, bp.y);
            fma2(acc2[3][0], a3, bp.x); fma2(acc2[3][1], a3, bp.y);
        }
    }

    float* dst = g_part + ((size_t)(split*16 + bh))*4096;
#pragma unroll
    for (int i = 0; i < 4; ++i) {
        float2 lo = upk(acc2[i][0]);
        float2 hi = upk(acc2[i][1]);
        *(float4*)(dst + (ty*4 + i)*64 + tx*4) = make_float4(lo.x, lo.y, hi.x, hi.y);
    }
}

// ---------------- split-reduce + causal softmax ----------------
__global__ void softmax_kernel()
{
    const int bh = blockIdx.y;
    const int t  = blockIdx.x;
    const int s  = threadIdx.x;

    float ssum = 0.f;
    for (int sp = 0; sp < 64; ++sp)
        ssum += g_part[((size_t)(sp*16 + bh)*64 + t)*64 + s];

    const float scale = rsqrtf(32768.0f);
    const bool valid = (s <= t);
    float logit = valid ? ssum * scale : -INFINITY;

    __shared__ float red[64];
    red[s] = logit;
    __syncthreads();
    for (int off = 32; off > 0; off >>= 1) {
        if (s < off) red[s] = fmaxf(red[s], red[s + off]);
        __syncthreads();
    }
    float mx = red[0];
    __syncthreads();
    float e = valid ? expf(logit - mx) : 0.f;
    red[s] = e;
    __syncthreads();
    for (int off = 32; off > 0; off >>= 1) {
        if (s < off) red[s] += red[s + off];
        __syncthreads();
    }
    float p = e / red[0];
    g_att[(bh*64 + s)*64 + t] = p;   // 0 for s > t
}

// ---------------- y = att @ V (packed over t, causal split) ----------------
// grid (128 d-chunks, 2 t-halves, 16 bh), block 256; thread = 1 d, 32 t (16 packed).
__global__ void __launch_bounds__(256) av_kernel()
{
    __shared__ __align__(16) float sa[64][32];   // att[s][t0+tt]
    const int bh = blockIdx.z;
    const int b  = bh >> 3, h = bh & 7;
    const int thalf = blockIdx.y;
    const int t0 = thalf * 32;
    const int smax = thalf ? 64 : 32;   // causal: lower t-half only needs s<32
    const int d  = blockIdx.x*256 + threadIdx.x;

    for (int i = threadIdx.x; i < smax*8; i += 256) {
        int s = i >> 3; int tg = i & 7;
        *(float4*)&sa[s][tg*4] = *(const float4*)(g_att + (bh*64 + s)*64 + t0 + tg*4);
    }
    __syncthreads();

    unsigned long long acc2[16];
#pragma unroll
    for (int g = 0; g < 16; ++g) acc2[g] = 0ULL;

    const size_t vbase = ((size_t)(b*64*16 + h*2))*HW + d;
#pragma unroll 2
    for (int s = 0; s < smax; ++s) {
        float v = g_v[vbase + (size_t)s*16*HW];
        unsigned long long v2 = pk2(v, v);
#pragma unroll
        for (int g = 0; g < 8; ++g) {
            ulonglong2 ap = *(const ulonglong2*)&sa[s][g*4];
            fma2(acc2[g*2+0], ap.x, v2);
            fma2(acc2[g*2+1], ap.y, v2);
        }
    }

#pragma unroll
    for (int g = 0; g < 16; ++g) {
        float2 o = upk(acc2[g]);
        int t = t0 + g*2;
        g_q[((size_t)((b*64 + t  )*16 + h*2))*HW + d] = o.x;   // y aliases g_q
        g_q[((size_t)((b*64 + t+1)*16 + h*2))*HW + d] = o.y;
    }
}

// ---------------- launch ----------------
extern "C" void kernel_launch(void* const* d_in, const int* in_sizes, int n_in,
                              void* d_out, int out_size)
{
    const float* x  = (const float*)d_in[0];
    const float* wq = (const float*)d_in[1];
    const float* bq = (const float*)d_in[2];
    const float* wk = (const float*)d_in[3];
    const float* bk = (const float*)d_in[4];
    const float* wv = (const float*)d_in[5];
    const float* bv = (const float*)d_in[6];
    const float* wo = (const float*)d_in[7];
    const float* bo = (const float*)d_in[8];
    float* out = (float*)d_out;

    const int smem3 = 48*160*8 + 5600*4 + 48*4;   // 84032 B
    const int smem1 = 16*160*8 + 5600*4 + 16*4;   // 42944 B
    cudaFuncSetAttribute(conv3x3_kernel<3>, cudaFuncAttributeMaxDynamicSharedMemorySize, smem3);
    cudaFuncSetAttribute(conv3x3_kernel<1>, cudaFuncAttributeMaxDynamicSharedMemorySize, smem1);

    dim3 cgrid(64, 128);
    conv3x3_kernel<3><<<cgrid, 256, smem3>>>(x, wq, bq, wk, bk, wv, bv, nullptr);
    qk_kernel<<<dim3(64, 16), 256>>>();
    softmax_kernel<<<dim3(64, 16), 64>>>();
    av_kernel<<<dim3(128, 2, 16), 256>>>();
    conv3x3_kernel<1><<<cgrid, 256, smem1>>>(nullptr, wo, bo, nullptr, nullptr,
                                             nullptr, nullptr, out);
}

// round 3
// speedup vs baseline: 1.1023x; 1.1023x over previous
#include <cuda_runtime.h>
#include <math.h>

// x: [B=2, T=64, C=16, H=128, W=128] f32; qkv conv 3x3 pad1 (16->16),
// nh=8, hc=2, D=32768; causal softmax T=64; out conv 3x3 (16->16).
#define HW 16384

// ---------------- packed fp32x2 helpers (FFMA2 path, 2x fp32 tput) --------
__device__ __forceinline__ unsigned long long pk2(float lo, float hi) {
    unsigned long long r;
    asm("mov.b64 %0, {%1, %2};"
        : "=l"(r) : "r"(__float_as_uint(lo)), "r"(__float_as_uint(hi)));
    return r;
}
__device__ __forceinline__ void fma2(unsigned long long& d,
                                     unsigned long long a, unsigned long long b) {
    asm("fma.rn.f32x2 %0, %1, %2, %0;" : "+l"(d) : "l"(a), "l"(b));
}
__device__ __forceinline__ float2 upk(unsigned long long v) {
    unsigned lo, hi;
    asm("mov.b64 {%0, %1}, %2;" : "=r"(lo), "=r"(hi) : "l"(v));
    return make_float2(__uint_as_float(lo), __uint_as_float(hi));
}

// ---------------- scratch ----------------
__device__ float g_q[2*64*16*16384];   // q, later reused as attention output y
__device__ float g_k[2*64*16*16384];
__device__ float g_v[2*64*16*16384];
__device__ float g_part[64*16*64*64];  // QK^T partials per k-split
__device__ float g_att[16*64*64];      // softmax probs, [bh][s][t]

// ---------------- 3x3 conv, one conv per block (grid.z selects q/k/v) -----
// Block 256 thr = 64 pixel-groups x 4 channel-groups. Tile 64(w) x 8(h).
// Thread = 8-pixel strip (4 packed pairs) x 4 output channels. FFMA2 inner.
template<bool FINAL>
__global__ void __launch_bounds__(256) conv3x3_kernel(
    const float* __restrict__ xin,
    const float* __restrict__ w0, const float* __restrict__ b0,
    const float* __restrict__ w1, const float* __restrict__ b1,
    const float* __restrict__ w2, const float* __restrict__ b2,
    float* __restrict__ out_final)
{
    extern __shared__ unsigned long long dynsmem[];
    unsigned long long* s_w2 = dynsmem;            // 16oc*16ic*10 packed (w,w)
    float* s_in = (float*)(dynsmem + 2560);        // 16ch x 10row x 68 (66 used)
    float* s_b  = s_in + 16*680;                   // 16 biases

    const int tid = threadIdx.x;
    const int bt  = blockIdx.y;                    // image 0..127
    const int cz  = blockIdx.z;                    // conv index (0..2 qkv, 0 out)
    const int th0 = (blockIdx.x >> 1) * 8;         // tile origin h
    const int tw0 = (blockIdx.x & 1) * 64;         // tile origin w

    const float* x = FINAL ? g_q : xin;
    const float* wsrc = FINAL ? w0 : (cz == 0 ? w0 : (cz == 1 ? w1 : w2));
    const float* bsrc = FINAL ? b0 : (cz == 0 ? b0 : (cz == 1 ? b1 : b2));
    float* outp = FINAL ? out_final : (cz == 0 ? g_q : (cz == 1 ? g_k : g_v));

    // stage weights duplicated into both f32x2 lanes: [oc*16+ic]*10 + j
    for (int idx = tid; idx < 16*144; idx += 256) {
        int oc = idx / 144;
        int r  = idx - oc*144;
        int ic = r / 9;
        int j  = r - ic*9;
        unsigned bb = __float_as_uint(wsrc[idx]);
        s_w2[(oc*16 + ic)*10 + j] = ((unsigned long long)bb << 32) | bb;
    }
    if (tid < 16) s_b[tid] = bsrc[tid];

    // stage input tile with halo: rows th0-1..th0+8, cols tw0-1..tw0+64
    for (int idx = tid; idx < 16*10*66; idx += 256) {
        int c   = idx / 660;
        int rem = idx - c*660;
        int yy  = rem / 66;
        int xx  = rem - yy*66;
        int gh  = th0 + yy - 1;
        int gw  = tw0 + xx - 1;
        float v = 0.f;
        if (gh >= 0 && gh < 128 && gw >= 0 && gw < 128)
            v = x[((size_t)bt*16 + c)*HW + gh*128 + gw];
        s_in[c*680 + yy*68 + xx] = v;
    }
    __syncthreads();

    const int pg  = tid & 63;          // pixel group
    const int cg  = tid >> 6;          // channel group 0..3 (4 oc each)
    const int sr  = pg >> 3;           // strip row 0..7
    const int scp = (pg & 7) * 8;      // strip col start (tile-local)

    unsigned long long acc2[4][4];
#pragma unroll
    for (int c = 0; c < 4; ++c) {
        float bb = s_b[cg*4 + c];
        unsigned long long b2v = pk2(bb, bb);
#pragma unroll
        for (int p = 0; p < 4; ++p) acc2[c][p] = b2v;
    }

    for (int ic = 0; ic < 16; ++ic) {
        const float* base = s_in + ic*680 + sr*68 + scp;  // rows sr..sr+2, 10 cols
        float p[3][10];
#pragma unroll
        for (int ky = 0; ky < 3; ++ky) {
            float4 a = *(const float4*)(base + ky*68);
            float4 b = *(const float4*)(base + ky*68 + 4);
            float2 c2 = *(const float2*)(base + ky*68 + 8);
            p[ky][0]=a.x; p[ky][1]=a.y; p[ky][2]=a.z; p[ky][3]=a.w;
            p[ky][4]=b.x; p[ky][5]=b.y; p[ky][6]=b.z; p[ky][7]=b.w;
            p[ky][8]=c2.x; p[ky][9]=c2.y;
        }
        unsigned long long pkk[3][9];
#pragma unroll
        for (int ky = 0; ky < 3; ++ky)
#pragma unroll
            for (int j = 0; j < 9; ++j)
                pkk[ky][j] = pk2(p[ky][j], p[ky][j+1]);

#pragma unroll
        for (int c = 0; c < 4; ++c) {
            const unsigned long long* wp = s_w2 + ((cg*4 + c)*16 + ic)*10;
            ulonglong2 w01 = *(const ulonglong2*)wp;
            ulonglong2 w23 = *(const ulonglong2*)(wp + 2);
            ulonglong2 w45 = *(const ulonglong2*)(wp + 4);
            ulonglong2 w67 = *(const ulonglong2*)(wp + 6);
            unsigned long long w8 = wp[8];
#pragma unroll
            for (int pp = 0; pp < 4; ++pp) {
                int q = pp*2;
                fma2(acc2[c][pp], pkk[0][q+0], w01.x);
                fma2(acc2[c][pp], pkk[0][q+1], w01.y);
                fma2(acc2[c][pp], pkk[0][q+2], w23.x);
                fma2(acc2[c][pp], pkk[1][q+0], w23.y);
                fma2(acc2[c][pp], pkk[1][q+1], w45.x);
                fma2(acc2[c][pp], pkk[1][q+2], w45.y);
                fma2(acc2[c][pp], pkk[2][q+0], w67.x);
                fma2(acc2[c][pp], pkk[2][q+1], w67.y);
                fma2(acc2[c][pp], pkk[2][q+2], w8);
            }
        }
    }

    const int oh = th0 + sr;
    const int ow = tw0 + scp;
#pragma unroll
    for (int c = 0; c < 4; ++c) {
        int oc = cg*4 + c;
        size_t off = ((size_t)bt*16 + oc)*HW + oh*128 + ow;
        float2 a = upk(acc2[c][0]);
        float2 b = upk(acc2[c][1]);
        float2 cc = upk(acc2[c][2]);
        float2 d = upk(acc2[c][3]);
        *(float4*)(outp + off)     = make_float4(a.x, a.y, b.x, b.y);
        *(float4*)(outp + off + 4) = make_float4(cc.x, cc.y, d.x, d.y);
    }
}

// ---------------- QK^T with K-split, FFMA2 inner ----------------
__global__ void __launch_bounds__(256) qk_kernel()
{
    __shared__ __align__(16) float Qs[64][68];
    __shared__ __align__(16) float Ks[64][68];
    const int bh = blockIdx.y;
    const int b  = bh >> 3, h = bh & 7;
    const int split = blockIdx.x;
    const int tid = threadIdx.x;
    const int ty = tid >> 4, tx = tid & 15;

    unsigned long long acc2[4][2];
#pragma unroll
    for (int i = 0; i < 4; ++i) { acc2[i][0] = 0ULL; acc2[i][1] = 0ULL; }

    for (int sub = 0; sub < 8; ++sub) {
        const int kc = split*512 + sub*64;
        __syncthreads();
        for (int i = tid; i < 1024; i += 256) {
            int t  = i >> 4;
            int kq = (i & 15) << 2;
            size_t base = ((size_t)((b*64 + t)*16 + h*2))*HW + kc + kq;
            float4 qa = *(const float4*)(g_q + base);
            float4 ka = *(const float4*)(g_k + base);
            Qs[kq+0][t] = qa.x; Qs[kq+1][t] = qa.y; Qs[kq+2][t] = qa.z; Qs[kq+3][t] = qa.w;
            Ks[kq+0][t] = ka.x; Ks[kq+1][t] = ka.y; Ks[kq+2][t] = ka.z; Ks[kq+3][t] = ka.w;
        }
        __syncthreads();
#pragma unroll 8
        for (int kk = 0; kk < 64; ++kk) {
            float4 a = *(const float4*)&Qs[kk][ty*4];
            ulonglong2 bp = *(const ulonglong2*)&Ks[kk][tx*4];
            unsigned long long a0 = pk2(a.x, a.x);
            unsigned long long a1 = pk2(a.y, a.y);
            unsigned long long a2 = pk2(a.z, a.z);
            unsigned long long a3 = pk2(a.w, a.w);
            fma2(acc2[0][0], a0, bp.x); fma2(acc2[0][1], a0, bp.y);
            fma2(acc2[1][0], a1, bp.x); fma2(acc2[1][1], a1, bp.y);
            fma2(acc2[2][0], a2, bp.x); fma2(acc2[2][1], a2, bp.y);
            fma2(acc2[3][0], a3, bp.x); fma2(acc2[3][1], a3, bp.y);
        }
    }

    float* dst = g_part + ((size_t)(split*16 + bh))*4096;
#pragma unroll
    for (int i = 0; i < 4; ++i) {
        float2 lo = upk(acc2[i][0]);
        float2 hi = upk(acc2[i][1]);
        *(float4*)(dst + (ty*4 + i)*64 + tx*4) = make_float4(lo.x, lo.y, hi.x, hi.y);
    }
}

// ---------------- split-reduce + causal softmax ----------------
__global__ void softmax_kernel()
{
    const int bh = blockIdx.y;
    const int t  = blockIdx.x;
    const int s  = threadIdx.x;

    float ssum = 0.f;
    for (int sp = 0; sp < 64; ++sp)
        ssum += g_part[((size_t)(sp*16 + bh)*64 + t)*64 + s];

    const float scale = rsqrtf(32768.0f);
    const bool valid = (s <= t);
    float logit = valid ? ssum * scale : -INFINITY;

    __shared__ float red[64];
    red[s] = logit;
    __syncthreads();
    for (int off = 32; off > 0; off >>= 1) {
        if (s < off) red[s] = fmaxf(red[s], red[s + off]);
        __syncthreads();
    }
    float mx = red[0];
    __syncthreads();
    float e = valid ? expf(logit - mx) : 0.f;
    red[s] = e;
    __syncthreads();
    for (int off = 32; off > 0; off >>= 1) {
        if (s < off) red[s] += red[s + off];
        __syncthreads();
    }
    float p = e / red[0];
    g_att[(bh*64 + s)*64 + t] = p;   // 0 for s > t
}

// ---------------- y = att @ V (packed over t, causal split) ----------------
__global__ void __launch_bounds__(256) av_kernel()
{
    __shared__ __align__(16) float sa[64][32];   // att[s][t0+tt]
    const int bh = blockIdx.z;
    const int b  = bh >> 3, h = bh & 7;
    const int thalf = blockIdx.y;
    const int t0 = thalf * 32;
    const int smax = thalf ? 64 : 32;   // causal: lower t-half only needs s<32
    const int d  = blockIdx.x*256 + threadIdx.x;

    for (int i = threadIdx.x; i < smax*8; i += 256) {
        int s = i >> 3; int tg = i & 7;
        *(float4*)&sa[s][tg*4] = *(const float4*)(g_att + (bh*64 + s)*64 + t0 + tg*4);
    }
    __syncthreads();

    unsigned long long acc2[16];
#pragma unroll
    for (int g = 0; g < 16; ++g) acc2[g] = 0ULL;

    const size_t vbase = ((size_t)(b*64*16 + h*2))*HW + d;
#pragma unroll 2
    for (int s = 0; s < smax; ++s) {
        float v = g_v[vbase + (size_t)s*16*HW];
        unsigned long long v2 = pk2(v, v);
#pragma unroll
        for (int g = 0; g < 8; ++g) {
            ulonglong2 ap = *(const ulonglong2*)&sa[s][g*4];
            fma2(acc2[g*2+0], ap.x, v2);
            fma2(acc2[g*2+1], ap.y, v2);
        }
    }

#pragma unroll
    for (int g = 0; g < 16; ++g) {
        float2 o = upk(acc2[g]);
        int t = t0 + g*2;
        g_q[((size_t)((b*64 + t  )*16 + h*2))*HW + d] = o.x;   // y aliases g_q
        g_q[((size_t)((b*64 + t+1)*16 + h*2))*HW + d] = o.y;
    }
}

// ---------------- launch ----------------
extern "C" void kernel_launch(void* const* d_in, const int* in_sizes, int n_in,
                              void* d_out, int out_size)
{
    const float* x  = (const float*)d_in[0];
    const float* wq = (const float*)d_in[1];
    const float* bq = (const float*)d_in[2];
    const float* wk = (const float*)d_in[3];
    const float* bk = (const float*)d_in[4];
    const float* wv = (const float*)d_in[5];
    const float* bv = (const float*)d_in[6];
    const float* wo = (const float*)d_in[7];
    const float* bo = (const float*)d_in[8];
    float* out = (float*)d_out;

    const int smem = 2560*8 + 16*680*4 + 16*4;   // 64064 B
    cudaFuncSetAttribute(conv3x3_kernel<false>, cudaFuncAttributeMaxDynamicSharedMemorySize, smem);
    cudaFuncSetAttribute(conv3x3_kernel<true>,  cudaFuncAttributeMaxDynamicSharedMemorySize, smem);

    conv3x3_kernel<false><<<dim3(32, 128, 3), 256, smem>>>(x, wq, bq, wk, bk, wv, bv, nullptr);
    qk_kernel<<<dim3(64, 16), 256>>>();
    softmax_kernel<<<dim3(64, 16), 64>>>();
    av_kernel<<<dim3(128, 2, 16), 256>>>();
    conv3x3_kernel<true><<<dim3(32, 128, 1), 256, smem>>>(nullptr, wo, bo, nullptr, nullptr,
                                                          nullptr, nullptr, out);
}